// round 3
// baseline (speedup 1.0000x reference)
#include <cuda_runtime.h>
#include <cuda_bf16.h>
#include <cstdint>

#define IN_H   1536
#define IN_W   1536
#define CH     16
#define OUT_H  768
#define OUT_W  768
#define HW     (IN_H * IN_W)
#define OHW    (OUT_H * OUT_W)

#define TX 64
#define TY 8
#define IN_COLS 129            // input cols per tile
#define IN_ROWS 17             // input rows per tile
#define ROW_PITCH 132          // float2: even[0..64] at 0..65, odd[0..63] at 66..129, pad
#define ODD_OFF 66
#define BUF_ELEMS (IN_ROWS * ROW_PITCH)        // 2244 float2 per ic-buffer
#define N_STAGE 9                              // ceil(17*129 / 256)
#define S_W_ELEMS (CH * 9 * CH)                // 2304 float2
#define SMEM_F2 (2 * BUF_ELEMS + S_W_ELEMS)
#define SMEM_BYTES (size_t)(SMEM_F2 * sizeof(float2) + 16 * sizeof(float))

typedef unsigned long long ull;

__device__ __forceinline__ ull fma2(ull a, ull b, ull c) {
    ull d;
    asm("fma.rn.f32x2 %0, %1, %2, %3;" : "=l"(d) : "l"(a), "l"(b), "l"(c));
    return d;
}
__device__ __forceinline__ void unpack2(ull v, float& lo, float& hi) {
    asm("mov.b64 {%0, %1}, %2;" : "=f"(lo), "=f"(hi) : "l"(v));
}
__device__ __forceinline__ ull lds2(const float2* p) {
    return *reinterpret_cast<const ull*>(p);
}

// Load one ic-chunk of (c,r) pairs into registers (global loads issued here).
__device__ __forceinline__ void stage_load(const float* __restrict__ lp,
                                           const float* __restrict__ up,
                                           int tid, int iy0, int ix0,
                                           float2 (&st)[N_STAGE], int (&tg)[N_STAGE]) {
    #pragma unroll
    for (int k = 0; k < N_STAGE; k++) {
        int j = tid + 256 * k;
        if (j < IN_ROWS * IN_COLS) {
            int row = j / IN_COLS;
            int col = j - row * IN_COLS;
            int iy = iy0 + row, ix = ix0 + col;
            float2 v = make_float2(0.f, 0.f);
            if ((unsigned)iy < IN_H && (unsigned)ix < IN_W) {
                int off = iy * IN_W + ix;
                float lv = lp[off];
                float uv = up[off];
                v = make_float2(0.5f * (lv + uv), 0.5f * (uv - lv));
            }
            st[k] = v;
            tg[k] = row * ROW_PITCH + (col >> 1) + ((col & 1) ? ODD_OFF : 0);
        } else {
            tg[k] = -1;
        }
    }
}

__device__ __forceinline__ void stage_store(float2* __restrict__ bp,
                                            const float2 (&st)[N_STAGE],
                                            const int (&tg)[N_STAGE]) {
    #pragma unroll
    for (int k = 0; k < N_STAGE; k++)
        if (tg[k] >= 0) bp[tg[k]] = st[k];
}

__global__ __launch_bounds__(256, 2)
void ibp_conv_kernel(const float* __restrict__ gl, const float* __restrict__ gu,
                     const float* __restrict__ gw, const float* __restrict__ gb,
                     float* __restrict__ out) {
    extern __shared__ float2 sm[];
    float2* s_buf = sm;                      // 2 ping-pong ic buffers
    float2* s_w   = sm + 2 * BUF_ELEMS;      // [(ic*9 + dy*3 + dx)*16 + oc] = (w,|w|)
    float*  s_b   = (float*)(s_w + S_W_ELEMS);

    const int tid = threadIdx.x;

    // stage weights + bias (once)
    for (int i = tid; i < S_W_ELEMS; i += 256) {
        int oc  = i / 144;
        int rem = i - oc * 144;
        float wv = gw[i];
        s_w[rem * 16 + oc] = make_float2(wv, fabsf(wv));
    }
    if (tid < 16) s_b[tid] = gb[tid];

    const int x0  = blockIdx.x * TX;
    const int y0  = blockIdx.y * TY;
    const int ix0 = 2 * x0 - 1;
    const int iy0 = 2 * y0 - 1;

    const int xg      = tid & 15;
    const int ty      = (tid >> 4) & 7;
    const int oc_base = (tid >> 7) * 8;

    ull acc[4][8];
    #pragma unroll
    for (int p = 0; p < 4; p++)
        #pragma unroll
        for (int o = 0; o < 8; o++) acc[p][o] = 0ull;

    float2 st[N_STAGE];
    int    tg[N_STAGE];

    // prologue: stage ic 0
    stage_load(gl, gu, tid, iy0, ix0, st, tg);
    stage_store(s_buf, st, tg);
    __syncthreads();

    #pragma unroll 1
    for (int ic = 0; ic < CH; ic++) {
        // issue global loads for next chunk (latency overlapped with compute below)
        if (ic < CH - 1)
            stage_load(gl + (ic + 1) * HW, gu + (ic + 1) * HW, tid, iy0, ix0, st, tg);

        const float2* base = s_buf + (ic & 1) * BUF_ELEMS;
        const float2* wtic = s_w + ic * 144 + oc_base;
        #pragma unroll
        for (int dy = 0; dy < 3; dy++) {
            const float2* rp = base + (2 * ty + dy) * ROW_PITCH;
            const float2* wt = wtic + dy * 48;
            #pragma unroll
            for (int dx = 0; dx < 3; dx++) {
                const float2* vp = rp + (dx == 1 ? ODD_OFF : (dx == 2 ? 1 : 0));
                ull vv[4];
                #pragma unroll
                for (int p = 0; p < 4; p++)
                    vv[p] = lds2(vp + xg + 16 * p);
                const ulonglong2* wp = (const ulonglong2*)(wt + dx * 16);
                #pragma unroll
                for (int q = 0; q < 4; q++) {
                    ulonglong2 w2 = wp[q];
                    #pragma unroll
                    for (int p = 0; p < 4; p++)
                        acc[p][2 * q] = fma2(vv[p], w2.x, acc[p][2 * q]);
                    #pragma unroll
                    for (int p = 0; p < 4; p++)
                        acc[p][2 * q + 1] = fma2(vv[p], w2.y, acc[p][2 * q + 1]);
                }
            }
        }
        // write next chunk into the other buffer (consumes staged regs)
        if (ic < CH - 1)
            stage_store(s_buf + ((ic + 1) & 1) * BUF_ELEMS, st, tg);
        __syncthreads();
    }

    // epilogue: bound_l = acc_c - acc_r + b ; bound_u = acc_c + acc_r + b
    const int oy = y0 + ty;
    #pragma unroll
    for (int o = 0; o < 8; o++) {
        const int oc = oc_base + o;
        const float b = s_b[oc];
        float* outl = out + oc * OHW + oy * OUT_W;
        float* outu = outl + CH * OHW;
        #pragma unroll
        for (int p = 0; p < 4; p++) {
            float ac, ar;
            unpack2(acc[p][o], ac, ar);
            const int ox = x0 + xg + 16 * p;
            outl[ox] = ac - ar + b;
            outu[ox] = ac + ar + b;
        }
    }
}

extern "C" void kernel_launch(void* const* d_in, const int* in_sizes, int n_in,
                              void* d_out, int out_size) {
    const float* l = (const float*)d_in[0];
    const float* u = (const float*)d_in[1];
    const float* w = (const float*)d_in[2];
    const float* b = (const float*)d_in[3];
    float* out = (float*)d_out;

    cudaFuncSetAttribute(ibp_conv_kernel,
                         cudaFuncAttributeMaxDynamicSharedMemorySize,
                         (int)SMEM_BYTES);
    dim3 grid(OUT_W / TX, OUT_H / TY);   // (12, 96)
    ibp_conv_kernel<<<grid, 256, SMEM_BYTES>>>(l, u, w, b, out);
}